// round 14
// baseline (speedup 1.0000x reference)
#include <cuda_runtime.h>
#include <cuda_bf16.h>
#include <math.h>
#include <stdint.h>

#define B_    8
#define C_    512
#define HW    4096            // 64*64
#define NPIX  (B_*HW)         // 32768
#define ELEMS (B_*C_*HW)      // 16777216
#define NBH   64              // B_*heads
#define NSPLIT 16

// ---------------- scratch (static device memory; no runtime allocation) ------
__device__ __nv_bfloat16 g_fm_hi[ELEMS];
__device__ __nv_bfloat16 g_fm_lo[ELEMS];
__device__ __nv_bfloat16 g_att_hi[ELEMS];
__device__ __nv_bfloat16 g_att_lo[ELEMS];
__device__ float g_q0 [ELEMS];
__device__ float g_k0 [ELEMS];
__device__ float g_v0 [ELEMS];
__device__ float g_qd [ELEMS];
__device__ float g_kd [ELEMS];     // softmax-normalized dwconv(k)
__device__ float g_vd [ELEMS];
__device__ float g_ctxp[NSPLIT * NBH * 64 * 64];
__device__ __nv_bfloat16 g_wt_hi[4][C_ * C_];   // [k][m] per tensor: q,k,v,out
__device__ __nv_bfloat16 g_wt_lo[4][C_ * C_];

// ---------------- streams/events (created pre-main, reused every call) -------
static cudaStream_t g_s2 = nullptr;
static cudaEvent_t  g_evRoot, g_evW;
struct StreamInit {
    StreamInit() {
        cudaStreamCreateWithFlags(&g_s2, cudaStreamNonBlocking);
        cudaEventCreateWithFlags(&g_evRoot, cudaEventDisableTiming);
        cudaEventCreateWithFlags(&g_evW, cudaEventDisableTiming);
    }
};
static StreamInit g_stream_init;

// ---------------- PTX helpers -------------------------------------------------
__device__ __forceinline__ uint32_t smem_u32(const void* p) {
    return (uint32_t)__cvta_generic_to_shared(p);
}
__device__ __forceinline__ void cp16(uint32_t dst, const void* src) {
    asm volatile("cp.async.cg.shared.global [%0], [%1], 16;\n" :: "r"(dst), "l"(src));
}
__device__ __forceinline__ void ldsm4t(uint32_t& r0, uint32_t& r1, uint32_t& r2, uint32_t& r3,
                                       uint32_t addr) {
    asm volatile("ldmatrix.sync.aligned.m8n8.x4.trans.shared.b16 {%0,%1,%2,%3}, [%4];\n"
                 : "=r"(r0), "=r"(r1), "=r"(r2), "=r"(r3) : "r"(addr));
}
__device__ __forceinline__ void mma16816(float* c, const uint32_t* a, const uint32_t* b) {
    asm volatile("mma.sync.aligned.m16n8k16.row.col.f32.bf16.bf16.f32 "
                 "{%0,%1,%2,%3}, {%4,%5,%6,%7}, {%8,%9}, {%0,%1,%2,%3};\n"
                 : "+f"(c[0]), "+f"(c[1]), "+f"(c[2]), "+f"(c[3])
                 : "r"(a[0]), "r"(a[1]), "r"(a[2]), "r"(a[3]), "r"(b[0]), "r"(b[1]));
}
__device__ __forceinline__ void split_bf16(float v, __nv_bfloat16& h, __nv_bfloat16& l) {
    h = __float2bfloat16(v);
    l = __float2bfloat16(v - __bfloat162float(h));
}

// ---------------- 0) weight transpose + bf16 split (all 4 weights, 1 launch) -
__global__ void __launch_bounds__(256) convw_k(const float* __restrict__ W0,
                                               const float* __restrict__ W1,
                                               const float* __restrict__ W2,
                                               const float* __restrict__ W3)
{
    __shared__ float tile[32][33];
    int wsel = blockIdx.z;
    const float* W = (wsel == 0) ? W0 : (wsel == 1) ? W1 : (wsel == 2) ? W2 : W3;
    __nv_bfloat16* Th = g_wt_hi[wsel];
    __nv_bfloat16* Tl = g_wt_lo[wsel];
    int mb = blockIdx.x * 32, kb = blockIdx.y * 32;
    int tx = threadIdx.x & 31, ty = threadIdx.x >> 5;   // 32 x 8
    #pragma unroll
    for (int i = 0; i < 32; i += 8)
        tile[ty + i][tx] = W[(mb + ty + i) * C_ + kb + tx];
    __syncthreads();
    #pragma unroll
    for (int i = 0; i < 32; i += 8) {
        float v = tile[tx][ty + i];                    // W[mb+tx][kb+ty+i]
        __nv_bfloat16 h, l; split_bf16(v, h, l);
        Th[(kb + ty + i) * C_ + mb + tx] = h;
        Tl[(kb + ty + i) * C_ + mb + tx] = l;
    }
}

// ---------------- 1) channel layernorm, two-pass high-parallelism ------------
__global__ void __launch_bounds__(256) ln_k(const float* __restrict__ x,
                                            const float* __restrict__ g)
{
    __shared__ float rs[4][64], rss[4][64], smean[64], sinv[64];
    int base = blockIdx.x * 64;
    int b = base >> 12, hw0 = base & 4095;
    const float* xp = x + (size_t)b * C_ * HW + hw0;
    int tid = threadIdx.x;
    int p = tid & 63, cg = tid >> 6;

    const float* tp = xp + (size_t)(cg * 128) * HW + p;
    float s = 0.f, ss = 0.f;
    #pragma unroll 8
    for (int c2 = 0; c2 < 128; c2++) {
        float v = tp[(size_t)c2 * HW];
        s += v; ss += v * v;
    }
    rs[cg][p] = s; rss[cg][p] = ss;
    __syncthreads();
    if (tid < 64) {
        float st  = rs[0][tid] + rs[1][tid] + rs[2][tid] + rs[3][tid];
        float sst = rss[0][tid] + rss[1][tid] + rss[2][tid] + rss[3][tid];
        float mean = st * (1.f / C_);
        float var  = sst * (1.f / C_) - mean * mean;
        smean[tid] = mean;
        sinv[tid]  = rsqrtf(var + 1e-5f);
    }
    __syncthreads();

    float mean = smean[p], inv = sinv[p];
    size_t ob = (size_t)b * C_ * HW + hw0 + (size_t)(cg * 128) * HW + p;
    #pragma unroll 8
    for (int c2 = 0; c2 < 128; c2++) {
        float v = (tp[(size_t)c2 * HW] - mean) * inv * __ldg(g + cg * 128 + c2);
        __nv_bfloat16 h, l; split_bf16(v, h, l);
        g_fm_hi[ob + (size_t)c2 * HW] = h;
        g_fm_lo[ob + (size_t)c2 * HW] = l;
    }
}

// ---------------- 2) bf16x3 HMMA GEMM, multi-tensor via blockIdx.y -----------
// blockIdx.y: tensor t = y>>2, m-tile (y&3)*128. Kernel body = round-9 proven.
#define STAGE_BYTES 65536
#define NSTAGE 3

__global__ void __launch_bounds__(256, 1) gemm_bf16x3_k(
    const __nv_bfloat16* __restrict__ Ahb, const __nv_bfloat16* __restrict__ Alb,
    const __nv_bfloat16* __restrict__ Bh, const __nv_bfloat16* __restrict__ Bl,
    float* __restrict__ C0, float* __restrict__ C1, float* __restrict__ C2)
{
    extern __shared__ char sm[];
    const int N = HW;
    const int z = blockIdx.z;
    const int ysel = blockIdx.y;
    const int t = ysel >> 2;
    const int m0 = (ysel & 3) * 128;
    const __nv_bfloat16* Ah = Ahb + (size_t)t * C_ * C_;
    const __nv_bfloat16* Al = Alb + (size_t)t * C_ * C_;
    float* Cg = (t == 0) ? C0 : (t == 1) ? C1 : C2;

    const __nv_bfloat16* Bhp = Bh + (size_t)z * C_ * HW;
    const __nv_bfloat16* Blp = Bl + (size_t)z * C_ * HW;
    float* Cp = Cg + (size_t)z * C_ * HW;
    const int n0 = blockIdx.x * 128;
    const int tid = threadIdx.x;
    const int r0 = tid >> 4;
    const int cc = tid & 15;

    const int wid = tid >> 5, lane = tid & 31;
    const int warpM = (wid & 1) * 64, warpN = (wid >> 1) * 32;
    const int j = lane >> 3, lr = lane & 7;

    float acc[4][4][4];
    #pragma unroll
    for (int mt = 0; mt < 4; mt++)
        #pragma unroll
        for (int nt = 0; nt < 4; nt++)
            #pragma unroll
            for (int q = 0; q < 4; q++) acc[mt][nt][q] = 0.f;

    auto tile_copy = [&](int stage, int k0) {
        char* base = sm + stage * STAGE_BYTES;
        #pragma unroll
        for (int i = 0; i < 4; i++) {
            int r = r0 + i * 16;
            uint32_t dsto = r * 256 + ((cc ^ (r & 7)) << 4);
            cp16(smem_u32(base + dsto),          Ah  + (size_t)(k0 + r) * C_ + m0 + cc * 8);
            cp16(smem_u32(base + 16384 + dsto),  Al  + (size_t)(k0 + r) * C_ + m0 + cc * 8);
            cp16(smem_u32(base + 32768 + dsto),  Bhp + (size_t)(k0 + r) * N  + n0 + cc * 8);
            cp16(smem_u32(base + 49152 + dsto),  Blp + (size_t)(k0 + r) * N  + n0 + cc * 8);
        }
        asm volatile("cp.async.commit_group;\n");
    };

    tile_copy(0, 0);
    tile_copy(1, 64);
    int stage_w = 2;
    for (int it = 0; it < 8; it++) {
        if (it + 2 < 8) {
            tile_copy(stage_w, (it + 2) * 64);
            stage_w = (stage_w + 1 == NSTAGE) ? 0 : stage_w + 1;
        } else {
            asm volatile("cp.async.commit_group;\n");
        }
        asm volatile("cp.async.wait_group 2;\n");
        __syncthreads();

        char* base = sm + (it % NSTAGE) * STAGE_BYTES;
        uint32_t aHiB = smem_u32(base);
        uint32_t aLoB = aHiB + 16384;
        uint32_t bHiB = aHiB + 32768;
        uint32_t bLoB = aHiB + 49152;

        #pragma unroll
        for (int kc = 0; kc < 4; kc++) {
            uint32_t aHi[4][4], aLo[4][4], bHi[4][2], bLo[4][2];
            int arow = kc * 16 + ((j >> 1) << 3) + lr;
            int asw  = arow & 7;
            #pragma unroll
            for (int mt = 0; mt < 4; mt++) {
                int achunk = ((warpM + mt * 16) >> 3) + (j & 1);
                uint32_t off = arow * 256 + ((achunk ^ asw) << 4);
                ldsm4t(aHi[mt][0], aHi[mt][1], aHi[mt][2], aHi[mt][3], aHiB + off);
                ldsm4t(aLo[mt][0], aLo[mt][1], aLo[mt][2], aLo[mt][3], aLoB + off);
            }
            int brow = kc * 16 + ((j & 1) << 3) + lr;
            int bsw  = brow & 7;
            #pragma unroll
            for (int nt2 = 0; nt2 < 2; nt2++) {
                int bchunk = ((warpN + nt2 * 16) >> 3) + (j >> 1);
                uint32_t off = brow * 256 + ((bchunk ^ bsw) << 4);
                ldsm4t(bHi[nt2 * 2][0], bHi[nt2 * 2][1],
                       bHi[nt2 * 2 + 1][0], bHi[nt2 * 2 + 1][1], bHiB + off);
                ldsm4t(bLo[nt2 * 2][0], bLo[nt2 * 2][1],
                       bLo[nt2 * 2 + 1][0], bLo[nt2 * 2 + 1][1], bLoB + off);
            }
            #pragma unroll
            for (int mt = 0; mt < 4; mt++)
                #pragma unroll
                for (int nt = 0; nt < 4; nt++) {
                    mma16816(acc[mt][nt], aHi[mt], bHi[nt]);
                    mma16816(acc[mt][nt], aLo[mt], bHi[nt]);
                    mma16816(acc[mt][nt], aHi[mt], bLo[nt]);
                }
        }
        __syncthreads();
    }

    int ml = lane >> 2, nl = (lane & 3) * 2;
    #pragma unroll
    for (int mt = 0; mt < 4; mt++) {
        int m = m0 + warpM + mt * 16 + ml;
        #pragma unroll
        for (int nt = 0; nt < 4; nt++) {
            int n = n0 + warpN + nt * 8 + nl;
            *(float2*)&Cp[(size_t)m * N + n]       = make_float2(acc[mt][nt][0], acc[mt][nt][1]);
            *(float2*)&Cp[(size_t)(m + 8) * N + n] = make_float2(acc[mt][nt][2], acc[mt][nt][3]);
        }
    }
}

// ---------------- 3) fused depthwise 3x3 (q,k,v in one launch) ---------------
__global__ void __launch_bounds__(256) dw3_k(const float* __restrict__ wq,
                                             const float* __restrict__ wk,
                                             const float* __restrict__ wv)
{
    __shared__ float sp[HW];
    __shared__ float red[256];
    int plane = blockIdx.x;
    int t     = blockIdx.y;
    const float* in; const float* w; float* out;
    if (t == 0)      { in = g_q0; w = wq; out = g_qd; }
    else if (t == 1) { in = g_k0; w = wk; out = g_kd; }
    else             { in = g_v0; w = wv; out = g_vd; }
    int c = plane & 511;
    const float* ip = in + (size_t)plane * HW;
    float* op = out + (size_t)plane * HW;
    int tid = threadIdx.x;

    #pragma unroll
    for (int i = 0; i < 4; i++)
        ((float4*)sp)[tid + i * 256] = ((const float4*)ip)[tid + i * 256];
    float wr[9];
    #pragma unroll
    for (int i = 0; i < 9; i++) wr[i] = w[c * 9 + i];
    __syncthreads();

    const int x  = tid & 63;
    const int rg = tid >> 6;
    const int yb = rg * 16;
    const bool xm = (x > 0), xp_ok = (x < 63);

    float a0, a1, a2, b0, b1, b2;
    if (yb > 0) {
        const float* row = sp + (yb - 1) * 64;
        a0 = xm ? row[x - 1] : 0.f; a1 = row[x]; a2 = xp_ok ? row[x + 1] : 0.f;
    } else { a0 = a1 = a2 = 0.f; }
    {
        const float* row = sp + yb * 64;
        b0 = xm ? row[x - 1] : 0.f; b1 = row[x]; b2 = xp_ok ? row[x + 1] : 0.f;
    }

    float o[16];
    float mx = -1e30f;
    #pragma unroll
    for (int i = 0; i < 16; i++) {
        int y = yb + i;
        float c0, c1, c2;
        if (y + 1 <= 63) {
            const float* row = sp + (y + 1) * 64;
            c0 = xm ? row[x - 1] : 0.f; c1 = row[x]; c2 = xp_ok ? row[x + 1] : 0.f;
        } else { c0 = c1 = c2 = 0.f; }
        float acc = a0 * wr[0] + a1 * wr[1] + a2 * wr[2]
                  + b0 * wr[3] + b1 * wr[4] + b2 * wr[5]
                  + c0 * wr[6] + c1 * wr[7] + c2 * wr[8];
        o[i] = acc;
        mx = fmaxf(mx, acc);
        a0 = b0; a1 = b1; a2 = b2;
        b0 = c0; b1 = c1; b2 = c2;
    }

    if (t == 1) {
        red[tid] = mx; __syncthreads();
        #pragma unroll
        for (int s = 128; s > 0; s >>= 1) {
            if (tid < s) red[tid] = fmaxf(red[tid], red[tid + s]);
            __syncthreads();
        }
        mx = red[0];
        __syncthreads();
        float s = 0.f;
        #pragma unroll
        for (int i = 0; i < 16; i++) { o[i] = __expf(o[i] - mx); s += o[i]; }
        red[tid] = s; __syncthreads();
        #pragma unroll
        for (int st = 128; st > 0; st >>= 1) {
            if (tid < st) red[tid] += red[tid + st];
            __syncthreads();
        }
        float rcp = 1.f / red[0];
        #pragma unroll
        for (int i = 0; i < 16; i++) op[(yb + i) * 64 + x] = o[i] * rcp;
    } else {
        #pragma unroll
        for (int i = 0; i < 16; i++) op[(yb + i) * 64 + x] = o[i];
    }
}

// ---------------- 5) ctx split-K partials (pure FMA) -------------------------
__global__ void __launch_bounds__(256) ctx_k()
{
    int bh    = blockIdx.y;
    int split = blockIdx.x;
    int b = bh >> 3, h = bh & 7;
    int nbase = split * 256;
    const float* kp = g_kd + (size_t)(b * C_ + h * 64) * HW;
    const float* vp = g_vd + (size_t)(b * C_ + h * 64) * HW;
    __shared__ float kT[64][65];
    __shared__ float vT[64][65];
    int tid = threadIdx.x;
    int d0 = (tid >> 4) * 4;
    int e0 = (tid & 15) * 4;
    float acc[4][4];
    #pragma unroll
    for (int i = 0; i < 4; i++)
        #pragma unroll
        for (int jx = 0; jx < 4; jx++) acc[i][jx] = 0.f;

    for (int chunk = 0; chunk < 4; chunk++) {
        int n0 = nbase + chunk * 64;
        for (int i = tid; i < 64 * 64; i += 256) {
            int d = i >> 6, nn = i & 63;
            kT[d][nn] = kp[d * HW + n0 + nn];
            vT[d][nn] = vp[d * HW + n0 + nn];
        }
        __syncthreads();
        #pragma unroll 8
        for (int nn = 0; nn < 64; nn++) {
            float kr[4], vr[4];
            #pragma unroll
            for (int i = 0; i < 4; i++) { kr[i] = kT[d0 + i][nn]; vr[i] = vT[e0 + i][nn]; }
            #pragma unroll
            for (int i = 0; i < 4; i++)
                #pragma unroll
                for (int jx = 0; jx < 4; jx++)
                    acc[i][jx] += kr[i] * vr[jx];
        }
        __syncthreads();
    }
    float* cp = g_ctxp + ((size_t)split * NBH + bh) * 4096;
    #pragma unroll
    for (int i = 0; i < 4; i++)
        #pragma unroll
        for (int jx = 0; jx < 4; jx++)
            cp[(d0 + i) * 64 + (e0 + jx)] = acc[i][jx];
}

// ---------------- 6) q softmax + q@ctx + silu -> bf16 hi/lo ------------------
__global__ void __launch_bounds__(256) attout_k()
{
    int bh = blockIdx.y;
    int b = bh >> 3, h = bh & 7;
    int n = blockIdx.x * 256 + threadIdx.x;
    __shared__ float ctx_s[64][64];
    for (int i = threadIdx.x; i < 4096; i += 256) {
        float s = 0.f;
        #pragma unroll
        for (int sp = 0; sp < NSPLIT; sp++)
            s += g_ctxp[((size_t)sp * NBH + bh) * 4096 + i];
        ctx_s[i >> 6][i & 63] = s;
    }
    __syncthreads();

    const float* qp = g_qd + (size_t)(b * C_ + h * 64) * HW + n;
    float q[64];
    float m = -1e30f;
    #pragma unroll
    for (int d = 0; d < 64; d++) { q[d] = qp[d * HW]; m = fmaxf(m, q[d]); }
    float s = 0.f;
    #pragma unroll
    for (int d = 0; d < 64; d++) { q[d] = __expf(q[d] - m); s += q[d]; }
    float r = 0.125f / s;
    #pragma unroll
    for (int d = 0; d < 64; d++) q[d] *= r;

    size_t obase = (size_t)(b * C_ + h * 64) * HW + n;
    #pragma unroll
    for (int ec = 0; ec < 4; ec++) {
        float acc[16];
        #pragma unroll
        for (int jx = 0; jx < 16; jx++) acc[jx] = 0.f;
        #pragma unroll
        for (int d = 0; d < 64; d++) {
            float qd = q[d];
            const float* crow = &ctx_s[d][ec * 16];
            #pragma unroll
            for (int jx = 0; jx < 16; jx++) acc[jx] += qd * crow[jx];
        }
        #pragma unroll
        for (int jx = 0; jx < 16; jx++) {
            float xv = acc[jx];
            float sg = 1.f / (1.f + __expf(-xv));
            float ov = xv * sg;
            __nv_bfloat16 hh, ll; split_bf16(ov, hh, ll);
            g_att_hi[obase + (size_t)(ec * 16 + jx) * HW] = hh;
            g_att_lo[obase + (size_t)(ec * 16 + jx) * HW] = ll;
        }
    }
}

// ---------------- host orchestration -----------------------------------------
template <typename T>
static T* symaddr(const void* sym)
{
    void* p = nullptr;
    cudaGetSymbolAddress(&p, sym);
    return (T*)p;
}

extern "C" void kernel_launch(void* const* d_in, const int* in_sizes, int n_in,
                              void* d_out, int out_size)
{
    const float* fmap = (const float*)d_in[0];
    const float* g    = (const float*)d_in[1];
    const float* wq1  = (const float*)d_in[2];
    const float* wqdw = (const float*)d_in[3];
    const float* wk1  = (const float*)d_in[4];
    const float* wkdw = (const float*)d_in[5];
    const float* wv1  = (const float*)d_in[6];
    const float* wvdw = (const float*)d_in[7];
    const float* wout = (const float*)d_in[8];
    float* out = (float*)d_out;

    __nv_bfloat16* fmh = symaddr<__nv_bfloat16>(g_fm_hi);
    __nv_bfloat16* fml = symaddr<__nv_bfloat16>(g_fm_lo);
    __nv_bfloat16* ath = symaddr<__nv_bfloat16>(g_att_hi);
    __nv_bfloat16* atl = symaddr<__nv_bfloat16>(g_att_lo);
    __nv_bfloat16* wth = symaddr<__nv_bfloat16>(g_wt_hi);
    __nv_bfloat16* wtl = symaddr<__nv_bfloat16>(g_wt_lo);
    float* q0  = symaddr<float>(g_q0);
    float* k0  = symaddr<float>(g_k0);
    float* v0  = symaddr<float>(g_v0);

    cudaFuncSetAttribute(gemm_bf16x3_k,
                         cudaFuncAttributeMaxDynamicSharedMemorySize, NSTAGE * STAGE_BYTES);

    cudaStream_t s0 = 0;          // capture stream
    cudaStream_t s2 = g_s2;

    // fork: side stream joins capture via event recorded on s0
    cudaEventRecord(g_evRoot, s0);
    cudaStreamWaitEvent(s2, g_evRoot, 0);

    // side: weight prep overlaps ln
    convw_k<<<dim3(16, 16, 4), 256, 0, s2>>>(wq1, wk1, wv1, wout);
    cudaEventRecord(g_evW, s2);

    // main: layernorm
    ln_k<<<512, 256, 0, s0>>>(fmap, g);
    cudaStreamWaitEvent(s0, g_evW, 0);

    // 2) fused q/k/v GEMM: one launch, grid (32, 12, 8)
    gemm_bf16x3_k<<<dim3(HW / 128, 12, B_), 256, NSTAGE * STAGE_BYTES, s0>>>(
        wth, wtl, fmh, fml, q0, k0, v0);

    // 3) fused depthwise 3x3 (q,k,v) + normalized k softmax, one launch
    dw3_k<<<dim3(B_ * C_, 3), 256, 0, s0>>>(wqdw, wkdw, wvdw);

    // 4) ctx = softk^T v
    ctx_k<<<dim3(NSPLIT, NBH), 256, 0, s0>>>();

    // 5) q softmax + q@ctx + silu
    attout_k<<<dim3(HW / 256, NBH), 256, 0, s0>>>();

    // 6) final pointwise conv -> d_out (t=0 path, grid.y=4)
    gemm_bf16x3_k<<<dim3(HW / 128, 4, B_), 256, NSTAGE * STAGE_BYTES, s0>>>(
        wth + 3 * C_ * C_, wtl + 3 * C_ * C_, ath, atl, out, out, out);

    (void)in_sizes; (void)n_in; (void)out_size;
}

// round 15
// speedup vs baseline: 1.0287x; 1.0287x over previous
#include <cuda_runtime.h>
#include <cuda_bf16.h>
#include <math.h>
#include <stdint.h>

#define B_    8
#define C_    512
#define HW    4096            // 64*64
#define NPIX  (B_*HW)         // 32768
#define ELEMS (B_*C_*HW)      // 16777216
#define NBH   64              // B_*heads
#define NSPLIT 16

// ---------------- scratch (static device memory; no runtime allocation) ------
__device__ __nv_bfloat16 g_fm_hi[ELEMS];
__device__ __nv_bfloat16 g_fm_lo[ELEMS];
__device__ __nv_bfloat16 g_att_hi[ELEMS];
__device__ __nv_bfloat16 g_att_lo[ELEMS];
__device__ float g_q0 [ELEMS];
__device__ float g_k0 [ELEMS];
__device__ float g_v0 [ELEMS];
__device__ float g_qd [ELEMS];
__device__ float g_kd [ELEMS];     // softmax-normalized dwconv(k)
__device__ float g_vd [ELEMS];
__device__ float g_ctxp[NSPLIT * NBH * 64 * 64];
__device__ float g_ctx [NBH * 64 * 64];          // reduced ctx
__device__ __nv_bfloat16 g_wt_hi[4][C_ * C_];
__device__ __nv_bfloat16 g_wt_lo[4][C_ * C_];

// ---------------- streams/events (created pre-main, reused every call) -------
static cudaStream_t g_s2 = nullptr;
static cudaEvent_t  g_evRoot, g_evW, g_evK, g_evV, g_evQ, g_evA;
struct StreamInit {
    StreamInit() {
        cudaStreamCreateWithFlags(&g_s2, cudaStreamNonBlocking);
        cudaEventCreateWithFlags(&g_evRoot, cudaEventDisableTiming);
        cudaEventCreateWithFlags(&g_evW, cudaEventDisableTiming);
        cudaEventCreateWithFlags(&g_evK, cudaEventDisableTiming);
        cudaEventCreateWithFlags(&g_evV, cudaEventDisableTiming);
        cudaEventCreateWithFlags(&g_evQ, cudaEventDisableTiming);
        cudaEventCreateWithFlags(&g_evA, cudaEventDisableTiming);
    }
};
static StreamInit g_stream_init;

// ---------------- PTX helpers -------------------------------------------------
__device__ __forceinline__ uint32_t smem_u32(const void* p) {
    return (uint32_t)__cvta_generic_to_shared(p);
}
__device__ __forceinline__ void cp16(uint32_t dst, const void* src) {
    asm volatile("cp.async.cg.shared.global [%0], [%1], 16;\n" :: "r"(dst), "l"(src));
}
__device__ __forceinline__ void ldsm4t(uint32_t& r0, uint32_t& r1, uint32_t& r2, uint32_t& r3,
                                       uint32_t addr) {
    asm volatile("ldmatrix.sync.aligned.m8n8.x4.trans.shared.b16 {%0,%1,%2,%3}, [%4];\n"
                 : "=r"(r0), "=r"(r1), "=r"(r2), "=r"(r3) : "r"(addr));
}
__device__ __forceinline__ void mma16816(float* c, const uint32_t* a, const uint32_t* b) {
    asm volatile("mma.sync.aligned.m16n8k16.row.col.f32.bf16.bf16.f32 "
                 "{%0,%1,%2,%3}, {%4,%5,%6,%7}, {%8,%9}, {%0,%1,%2,%3};\n"
                 : "+f"(c[0]), "+f"(c[1]), "+f"(c[2]), "+f"(c[3])
                 : "r"(a[0]), "r"(a[1]), "r"(a[2]), "r"(a[3]), "r"(b[0]), "r"(b[1]));
}
__device__ __forceinline__ void split_bf16(float v, __nv_bfloat16& h, __nv_bfloat16& l) {
    h = __float2bfloat16(v);
    l = __float2bfloat16(v - __bfloat162float(h));
}

// ---------------- 0) weight transpose + bf16 split (all 4 weights, 1 launch) -
__global__ void __launch_bounds__(256) convw_k(const float* __restrict__ W0,
                                               const float* __restrict__ W1,
                                               const float* __restrict__ W2,
                                               const float* __restrict__ W3)
{
    __shared__ float tile[32][33];
    int wsel = blockIdx.z;
    const float* W = (wsel == 0) ? W0 : (wsel == 1) ? W1 : (wsel == 2) ? W2 : W3;
    __nv_bfloat16* Th = g_wt_hi[wsel];
    __nv_bfloat16* Tl = g_wt_lo[wsel];
    int mb = blockIdx.x * 32, kb = blockIdx.y * 32;
    int tx = threadIdx.x & 31, ty = threadIdx.x >> 5;   // 32 x 8
    #pragma unroll
    for (int i = 0; i < 32; i += 8)
        tile[ty + i][tx] = W[(mb + ty + i) * C_ + kb + tx];
    __syncthreads();
    #pragma unroll
    for (int i = 0; i < 32; i += 8) {
        float v = tile[tx][ty + i];                    // W[mb+tx][kb+ty+i]
        __nv_bfloat16 h, l; split_bf16(v, h, l);
        Th[(kb + ty + i) * C_ + mb + tx] = h;
        Tl[(kb + ty + i) * C_ + mb + tx] = l;
    }
}

// ---------------- 1) channel layernorm, two-pass high-parallelism ------------
__global__ void __launch_bounds__(256) ln_k(const float* __restrict__ x,
                                            const float* __restrict__ g)
{
    __shared__ float rs[4][64], rss[4][64], smean[64], sinv[64];
    int base = blockIdx.x * 64;
    int b = base >> 12, hw0 = base & 4095;
    const float* xp = x + (size_t)b * C_ * HW + hw0;
    int tid = threadIdx.x;
    int p = tid & 63, cg = tid >> 6;

    const float* tp = xp + (size_t)(cg * 128) * HW + p;
    float s = 0.f, ss = 0.f;
    #pragma unroll 8
    for (int c2 = 0; c2 < 128; c2++) {
        float v = tp[(size_t)c2 * HW];
        s += v; ss += v * v;
    }
    rs[cg][p] = s; rss[cg][p] = ss;
    __syncthreads();
    if (tid < 64) {
        float st  = rs[0][tid] + rs[1][tid] + rs[2][tid] + rs[3][tid];
        float sst = rss[0][tid] + rss[1][tid] + rss[2][tid] + rss[3][tid];
        float mean = st * (1.f / C_);
        float var  = sst * (1.f / C_) - mean * mean;
        smean[tid] = mean;
        sinv[tid]  = rsqrtf(var + 1e-5f);
    }
    __syncthreads();

    float mean = smean[p], inv = sinv[p];
    size_t ob = (size_t)b * C_ * HW + hw0 + (size_t)(cg * 128) * HW + p;
    #pragma unroll 8
    for (int c2 = 0; c2 < 128; c2++) {
        float v = (tp[(size_t)c2 * HW] - mean) * inv * __ldg(g + cg * 128 + c2);
        __nv_bfloat16 h, l; split_bf16(v, h, l);
        g_fm_hi[ob + (size_t)c2 * HW] = h;
        g_fm_lo[ob + (size_t)c2 * HW] = l;
    }
}

// ---------------- 2) bf16x3 HMMA GEMM, 3-stage cp.async (round-9 proven) -----
#define STAGE_BYTES 65536
#define NSTAGE 3

__global__ void __launch_bounds__(256, 1) gemm_bf16x3_k(
    const __nv_bfloat16* __restrict__ Ah, const __nv_bfloat16* __restrict__ Al,
    const __nv_bfloat16* __restrict__ Bh, const __nv_bfloat16* __restrict__ Bl,
    float* __restrict__ Cg)
{
    extern __shared__ char sm[];
    const int N = HW;
    const int z = blockIdx.z;
    const __nv_bfloat16* Bhp = Bh + (size_t)z * C_ * HW;
    const __nv_bfloat16* Blp = Bl + (size_t)z * C_ * HW;
    float* Cp = Cg + (size_t)z * C_ * HW;
    const int m0 = blockIdx.y * 128, n0 = blockIdx.x * 128;
    const int tid = threadIdx.x;
    const int r0 = tid >> 4;
    const int cc = tid & 15;

    const int wid = tid >> 5, lane = tid & 31;
    const int warpM = (wid & 1) * 64, warpN = (wid >> 1) * 32;
    const int j = lane >> 3, lr = lane & 7;

    float acc[4][4][4];
    #pragma unroll
    for (int mt = 0; mt < 4; mt++)
        #pragma unroll
        for (int nt = 0; nt < 4; nt++)
            #pragma unroll
            for (int q = 0; q < 4; q++) acc[mt][nt][q] = 0.f;

    auto tile_copy = [&](int stage, int k0) {
        char* base = sm + stage * STAGE_BYTES;
        #pragma unroll
        for (int i = 0; i < 4; i++) {
            int r = r0 + i * 16;
            uint32_t dsto = r * 256 + ((cc ^ (r & 7)) << 4);
            cp16(smem_u32(base + dsto),          Ah  + (size_t)(k0 + r) * C_ + m0 + cc * 8);
            cp16(smem_u32(base + 16384 + dsto),  Al  + (size_t)(k0 + r) * C_ + m0 + cc * 8);
            cp16(smem_u32(base + 32768 + dsto),  Bhp + (size_t)(k0 + r) * N  + n0 + cc * 8);
            cp16(smem_u32(base + 49152 + dsto),  Blp + (size_t)(k0 + r) * N  + n0 + cc * 8);
        }
        asm volatile("cp.async.commit_group;\n");
    };

    tile_copy(0, 0);
    tile_copy(1, 64);
    int stage_w = 2;
    for (int it = 0; it < 8; it++) {
        if (it + 2 < 8) {
            tile_copy(stage_w, (it + 2) * 64);
            stage_w = (stage_w + 1 == NSTAGE) ? 0 : stage_w + 1;
        } else {
            asm volatile("cp.async.commit_group;\n");
        }
        asm volatile("cp.async.wait_group 2;\n");
        __syncthreads();

        char* base = sm + (it % NSTAGE) * STAGE_BYTES;
        uint32_t aHiB = smem_u32(base);
        uint32_t aLoB = aHiB + 16384;
        uint32_t bHiB = aHiB + 32768;
        uint32_t bLoB = aHiB + 49152;

        #pragma unroll
        for (int kc = 0; kc < 4; kc++) {
            uint32_t aHi[4][4], aLo[4][4], bHi[4][2], bLo[4][2];
            int arow = kc * 16 + ((j >> 1) << 3) + lr;
            int asw  = arow & 7;
            #pragma unroll
            for (int mt = 0; mt < 4; mt++) {
                int achunk = ((warpM + mt * 16) >> 3) + (j & 1);
                uint32_t off = arow * 256 + ((achunk ^ asw) << 4);
                ldsm4t(aHi[mt][0], aHi[mt][1], aHi[mt][2], aHi[mt][3], aHiB + off);
                ldsm4t(aLo[mt][0], aLo[mt][1], aLo[mt][2], aLo[mt][3], aLoB + off);
            }
            int brow = kc * 16 + ((j & 1) << 3) + lr;
            int bsw  = brow & 7;
            #pragma unroll
            for (int nt2 = 0; nt2 < 2; nt2++) {
                int bchunk = ((warpN + nt2 * 16) >> 3) + (j >> 1);
                uint32_t off = brow * 256 + ((bchunk ^ bsw) << 4);
                ldsm4t(bHi[nt2 * 2][0], bHi[nt2 * 2][1],
                       bHi[nt2 * 2 + 1][0], bHi[nt2 * 2 + 1][1], bHiB + off);
                ldsm4t(bLo[nt2 * 2][0], bLo[nt2 * 2][1],
                       bLo[nt2 * 2 + 1][0], bLo[nt2 * 2 + 1][1], bLoB + off);
            }
            #pragma unroll
            for (int mt = 0; mt < 4; mt++)
                #pragma unroll
                for (int nt = 0; nt < 4; nt++) {
                    mma16816(acc[mt][nt], aHi[mt], bHi[nt]);
                    mma16816(acc[mt][nt], aLo[mt], bHi[nt]);
                    mma16816(acc[mt][nt], aHi[mt], bLo[nt]);
                }
        }
        __syncthreads();
    }

    int ml = lane >> 2, nl = (lane & 3) * 2;
    #pragma unroll
    for (int mt = 0; mt < 4; mt++) {
        int m = m0 + warpM + mt * 16 + ml;
        #pragma unroll
        for (int nt = 0; nt < 4; nt++) {
            int n = n0 + warpN + nt * 8 + nl;
            *(float2*)&Cp[(size_t)m * N + n]       = make_float2(acc[mt][nt][0], acc[mt][nt][1]);
            *(float2*)&Cp[(size_t)(m + 8) * N + n] = make_float2(acc[mt][nt][2], acc[mt][nt][3]);
        }
    }
}

// ---------------- 3) depthwise 3x3 (single tensor) + optional k softmax ------
template <bool DO_SOFTMAX>
__global__ void __launch_bounds__(256) dw_k(const float* __restrict__ in,
                                            const float* __restrict__ w,
                                            float* __restrict__ out)
{
    __shared__ float sp[HW];
    __shared__ float red[256];
    int plane = blockIdx.x;
    int c = plane & 511;
    const float* ip = in + (size_t)plane * HW;
    float* op = out + (size_t)plane * HW;
    int tid = threadIdx.x;

    #pragma unroll
    for (int i = 0; i < 4; i++)
        ((float4*)sp)[tid + i * 256] = ((const float4*)ip)[tid + i * 256];
    float wr[9];
    #pragma unroll
    for (int i = 0; i < 9; i++) wr[i] = w[c * 9 + i];
    __syncthreads();

    const int x  = tid & 63;
    const int rg = tid >> 6;
    const int yb = rg * 16;
    const bool xm = (x > 0), xp_ok = (x < 63);

    float a0, a1, a2, b0, b1, b2;
    if (yb > 0) {
        const float* row = sp + (yb - 1) * 64;
        a0 = xm ? row[x - 1] : 0.f; a1 = row[x]; a2 = xp_ok ? row[x + 1] : 0.f;
    } else { a0 = a1 = a2 = 0.f; }
    {
        const float* row = sp + yb * 64;
        b0 = xm ? row[x - 1] : 0.f; b1 = row[x]; b2 = xp_ok ? row[x + 1] : 0.f;
    }

    float o[16];
    float mx = -1e30f;
    #pragma unroll
    for (int i = 0; i < 16; i++) {
        int y = yb + i;
        float c0, c1, c2;
        if (y + 1 <= 63) {
            const float* row = sp + (y + 1) * 64;
            c0 = xm ? row[x - 1] : 0.f; c1 = row[x]; c2 = xp_ok ? row[x + 1] : 0.f;
        } else { c0 = c1 = c2 = 0.f; }
        float acc = a0 * wr[0] + a1 * wr[1] + a2 * wr[2]
                  + b0 * wr[3] + b1 * wr[4] + b2 * wr[5]
                  + c0 * wr[6] + c1 * wr[7] + c2 * wr[8];
        o[i] = acc;
        mx = fmaxf(mx, acc);
        a0 = b0; a1 = b1; a2 = b2;
        b0 = c0; b1 = c1; b2 = c2;
    }

    if (DO_SOFTMAX) {
        red[tid] = mx; __syncthreads();
        #pragma unroll
        for (int s = 128; s > 0; s >>= 1) {
            if (tid < s) red[tid] = fmaxf(red[tid], red[tid + s]);
            __syncthreads();
        }
        mx = red[0];
        __syncthreads();
        float s = 0.f;
        #pragma unroll
        for (int i = 0; i < 16; i++) { o[i] = __expf(o[i] - mx); s += o[i]; }
        red[tid] = s; __syncthreads();
        #pragma unroll
        for (int st = 128; st > 0; st >>= 1) {
            if (tid < st) red[tid] += red[tid + st];
            __syncthreads();
        }
        float rcp = 1.f / red[0];
        #pragma unroll
        for (int i = 0; i < 16; i++) op[(yb + i) * 64 + x] = o[i] * rcp;
    } else {
        #pragma unroll
        for (int i = 0; i < 16; i++) op[(yb + i) * 64 + x] = o[i];
    }
}

// ---------------- 5) ctx split-K partials (pure FMA) -------------------------
__global__ void __launch_bounds__(256) ctx_k()
{
    int bh    = blockIdx.y;
    int split = blockIdx.x;
    int b = bh >> 3, h = bh & 7;
    int nbase = split * 256;
    const float* kp = g_kd + (size_t)(b * C_ + h * 64) * HW;
    const float* vp = g_vd + (size_t)(b * C_ + h * 64) * HW;
    __shared__ float kT[64][65];
    __shared__ float vT[64][65];
    int tid = threadIdx.x;
    int d0 = (tid >> 4) * 4;
    int e0 = (tid & 15) * 4;
    float acc[4][4];
    #pragma unroll
    for (int i = 0; i < 4; i++)
        #pragma unroll
        for (int jx = 0; jx < 4; jx++) acc[i][jx] = 0.f;

    for (int chunk = 0; chunk < 4; chunk++) {
        int n0 = nbase + chunk * 64;
        for (int i = tid; i < 64 * 64; i += 256) {
            int d = i >> 6, nn = i & 63;
            kT[d][nn] = kp[d * HW + n0 + nn];
            vT[d][nn] = vp[d * HW + n0 + nn];
        }
        __syncthreads();
        #pragma unroll 8
        for (int nn = 0; nn < 64; nn++) {
            float kr[4], vr[4];
            #pragma unroll
            for (int i = 0; i < 4; i++) { kr[i] = kT[d0 + i][nn]; vr[i] = vT[e0 + i][nn]; }
            #pragma unroll
            for (int i = 0; i < 4; i++)
                #pragma unroll
                for (int jx = 0; jx < 4; jx++)
                    acc[i][jx] += kr[i] * vr[jx];
        }
        __syncthreads();
    }
    float* cp = g_ctxp + ((size_t)split * NBH + bh) * 4096;
    #pragma unroll
    for (int i = 0; i < 4; i++)
        #pragma unroll
        for (int jx = 0; jx < 4; jx++)
            cp[(d0 + i) * 64 + (e0 + jx)] = acc[i][jx];
}

// ---------------- 5b) reduce split-K partials once ---------------------------
__global__ void __launch_bounds__(256) ctxred_k()
{
    int bh = blockIdx.x;
    int tid = threadIdx.x;
    #pragma unroll
    for (int i = 0; i < 16; i++) {
        int idx = tid + i * 256;
        float s = 0.f;
        #pragma unroll
        for (int sp = 0; sp < NSPLIT; sp++)
            s += g_ctxp[((size_t)sp * NBH + bh) * 4096 + idx];
        g_ctx[(size_t)bh * 4096 + idx] = s;
    }
}

// ---------------- 6) q softmax + q@ctx + silu -> bf16 hi/lo ------------------
__global__ void __launch_bounds__(256) attout_k()
{
    int bh = blockIdx.y;
    int b = bh >> 3, h = bh & 7;
    int n = blockIdx.x * 256 + threadIdx.x;
    __shared__ float ctx_s[64][64];
    for (int i = threadIdx.x; i < 4096; i += 256)
        ctx_s[i >> 6][i & 63] = g_ctx[(size_t)bh * 4096 + i];
    __syncthreads();

    const float* qp = g_qd + (size_t)(b * C_ + h * 64) * HW + n;
    float q[64];
    float m = -1e30f;
    #pragma unroll
    for (int d = 0; d < 64; d++) { q[d] = qp[d * HW]; m = fmaxf(m, q[d]); }
    float s = 0.f;
    #pragma unroll
    for (int d = 0; d < 64; d++) { q[d] = __expf(q[d] - m); s += q[d]; }
    float r = 0.125f / s;
    #pragma unroll
    for (int d = 0; d < 64; d++) q[d] *= r;

    size_t obase = (size_t)(b * C_ + h * 64) * HW + n;
    #pragma unroll
    for (int ec = 0; ec < 4; ec++) {
        float acc[16];
        #pragma unroll
        for (int jx = 0; jx < 16; jx++) acc[jx] = 0.f;
        #pragma unroll
        for (int d = 0; d < 64; d++) {
            float qd = q[d];
            const float* crow = &ctx_s[d][ec * 16];
            #pragma unroll
            for (int jx = 0; jx < 16; jx++) acc[jx] += qd * crow[jx];
        }
        #pragma unroll
        for (int jx = 0; jx < 16; jx++) {
            float xv = acc[jx];
            float sg = 1.f / (1.f + __expf(-xv));
            float ov = xv * sg;
            __nv_bfloat16 hh, ll; split_bf16(ov, hh, ll);
            g_att_hi[obase + (size_t)(ec * 16 + jx) * HW] = hh;
            g_att_lo[obase + (size_t)(ec * 16 + jx) * HW] = ll;
        }
    }
}

// ---------------- host orchestration -----------------------------------------
template <typename T>
static T* symaddr(const void* sym)
{
    void* p = nullptr;
    cudaGetSymbolAddress(&p, sym);
    return (T*)p;
}

extern "C" void kernel_launch(void* const* d_in, const int* in_sizes, int n_in,
                              void* d_out, int out_size)
{
    const float* fmap = (const float*)d_in[0];
    const float* g    = (const float*)d_in[1];
    const float* wq1  = (const float*)d_in[2];
    const float* wqdw = (const float*)d_in[3];
    const float* wk1  = (const float*)d_in[4];
    const float* wkdw = (const float*)d_in[5];
    const float* wv1  = (const float*)d_in[6];
    const float* wvdw = (const float*)d_in[7];
    const float* wout = (const float*)d_in[8];
    float* out = (float*)d_out;

    __nv_bfloat16* fmh = symaddr<__nv_bfloat16>(g_fm_hi);
    __nv_bfloat16* fml = symaddr<__nv_bfloat16>(g_fm_lo);
    __nv_bfloat16* ath = symaddr<__nv_bfloat16>(g_att_hi);
    __nv_bfloat16* atl = symaddr<__nv_bfloat16>(g_att_lo);
    __nv_bfloat16* wth = symaddr<__nv_bfloat16>(g_wt_hi);
    __nv_bfloat16* wtl = symaddr<__nv_bfloat16>(g_wt_lo);
    float* q0  = symaddr<float>(g_q0);
    float* k0  = symaddr<float>(g_k0);
    float* v0  = symaddr<float>(g_v0);
    float* qd  = symaddr<float>(g_qd);
    float* kd  = symaddr<float>(g_kd);
    float* vd  = symaddr<float>(g_vd);

    cudaFuncSetAttribute(gemm_bf16x3_k,
                         cudaFuncAttributeMaxDynamicSharedMemorySize, NSTAGE * STAGE_BYTES);

    cudaStream_t s0 = 0;          // capture stream
    cudaStream_t s2 = g_s2;

    // fork: side stream joins capture via event recorded on s0
    cudaEventRecord(g_evRoot, s0);
    cudaStreamWaitEvent(s2, g_evRoot, 0);

    // side: weight prep (overlaps ln on s0)
    convw_k<<<dim3(16, 16, 4), 256, 0, s2>>>(wq1, wk1, wv1, wout);
    cudaEventRecord(g_evW, s2);

    // main: layernorm
    ln_k<<<512, 256, 0, s0>>>(fmap, g);
    cudaStreamWaitEvent(s0, g_evW, 0);

    dim3 gg(HW / 128, C_ / 128, B_);

    // main: GEMM chain k -> v -> q
    gemm_bf16x3_k<<<gg, 256, NSTAGE * STAGE_BYTES, s0>>>(wth + 1 * C_ * C_, wtl + 1 * C_ * C_, fmh, fml, k0);
    cudaEventRecord(g_evK, s0);
    gemm_bf16x3_k<<<gg, 256, NSTAGE * STAGE_BYTES, s0>>>(wth + 2 * C_ * C_, wtl + 2 * C_ * C_, fmh, fml, v0);
    cudaEventRecord(g_evV, s0);
    gemm_bf16x3_k<<<gg, 256, NSTAGE * STAGE_BYTES, s0>>>(wth + 0 * C_ * C_, wtl + 0 * C_ * C_, fmh, fml, q0);
    cudaEventRecord(g_evQ, s0);

    // side stream: glue overlapped with GEMMs
    cudaStreamWaitEvent(s2, g_evK, 0);
    dw_k<true><<<B_ * C_, 256, 0, s2>>>(k0, wkdw, kd);          // overlaps GEMM_v
    cudaStreamWaitEvent(s2, g_evV, 0);
    dw_k<false><<<B_ * C_, 256, 0, s2>>>(v0, wvdw, vd);         // overlaps GEMM_q
    ctx_k<<<dim3(NSPLIT, NBH), 256, 0, s2>>>();                 // overlaps GEMM_q
    ctxred_k<<<NBH, 256, 0, s2>>>();                            // overlaps GEMM_q
    cudaStreamWaitEvent(s2, g_evQ, 0);
    dw_k<false><<<B_ * C_, 256, 0, s2>>>(q0, wqdw, qd);
    attout_k<<<dim3(HW / 256, NBH), 256, 0, s2>>>();
    cudaEventRecord(g_evA, s2);

    // main: final pointwise conv -> d_out (join)
    cudaStreamWaitEvent(s0, g_evA, 0);
    gemm_bf16x3_k<<<gg, 256, NSTAGE * STAGE_BYTES, s0>>>(wth + 3 * C_ * C_, wtl + 3 * C_ * C_, ath, atl, out);

    (void)in_sizes; (void)n_in; (void)out_size;
}

// round 16
// speedup vs baseline: 1.2370x; 1.2026x over previous
#include <cuda_runtime.h>
#include <cuda_bf16.h>
#include <cuda_fp16.h>
#include <math.h>
#include <stdint.h>

#define B_    8
#define C_    512
#define HW    4096            // 64*64
#define NPIX  (B_*HW)         // 32768
#define ELEMS (B_*C_*HW)      // 16777216
#define NBH   64              // B_*heads
#define NSPLIT 16

// ---------------- scratch (static device memory; no runtime allocation) ------
__device__ __half g_fm_hi[ELEMS];
__device__ __half g_fm_lo[ELEMS];
__device__ __half g_att_hi[ELEMS];
__device__ __half g_att_lo[ELEMS];
__device__ float g_q0 [ELEMS];
__device__ float g_k0 [ELEMS];
__device__ float g_v0 [ELEMS];
__device__ float g_qd [ELEMS];
__device__ float g_kd [ELEMS];     // softmax-normalized dwconv(k)
__device__ float g_vd [ELEMS];
__device__ float g_ctxp[NSPLIT * NBH * 64 * 64];
__device__ float g_ctx [NBH * 64 * 64];          // reduced ctx
__device__ __half g_wt[4][C_ * C_];              // [k][m] single fp16, q|k|v|out

// ---------------- streams/events (created pre-main, reused every call) -------
static cudaStream_t g_s2 = nullptr;
static cudaEvent_t  g_evRoot, g_evW, g_evK, g_evV, g_evQ, g_evA;
struct StreamInit {
    StreamInit() {
        cudaStreamCreateWithFlags(&g_s2, cudaStreamNonBlocking);
        cudaEventCreateWithFlags(&g_evRoot, cudaEventDisableTiming);
        cudaEventCreateWithFlags(&g_evW, cudaEventDisableTiming);
        cudaEventCreateWithFlags(&g_evK, cudaEventDisableTiming);
        cudaEventCreateWithFlags(&g_evV, cudaEventDisableTiming);
        cudaEventCreateWithFlags(&g_evQ, cudaEventDisableTiming);
        cudaEventCreateWithFlags(&g_evA, cudaEventDisableTiming);
    }
};
static StreamInit g_stream_init;

// ---------------- PTX helpers -------------------------------------------------
__device__ __forceinline__ uint32_t smem_u32(const void* p) {
    return (uint32_t)__cvta_generic_to_shared(p);
}
__device__ __forceinline__ void cp16(uint32_t dst, const void* src) {
    asm volatile("cp.async.cg.shared.global [%0], [%1], 16;\n" :: "r"(dst), "l"(src));
}
__device__ __forceinline__ void ldsm4t(uint32_t& r0, uint32_t& r1, uint32_t& r2, uint32_t& r3,
                                       uint32_t addr) {
    asm volatile("ldmatrix.sync.aligned.m8n8.x4.trans.shared.b16 {%0,%1,%2,%3}, [%4];\n"
                 : "=r"(r0), "=r"(r1), "=r"(r2), "=r"(r3) : "r"(addr));
}
__device__ __forceinline__ void mma16816(float* c, const uint32_t* a, const uint32_t* b) {
    asm volatile("mma.sync.aligned.m16n8k16.row.col.f32.f16.f16.f32 "
                 "{%0,%1,%2,%3}, {%4,%5,%6,%7}, {%8,%9}, {%0,%1,%2,%3};\n"
                 : "+f"(c[0]), "+f"(c[1]), "+f"(c[2]), "+f"(c[3])
                 : "r"(a[0]), "r"(a[1]), "r"(a[2]), "r"(a[3]), "r"(b[0]), "r"(b[1]));
}
__device__ __forceinline__ void split_fp16(float v, __half& h, __half& l) {
    h = __float2half(v);
    l = __float2half(v - __half2float(h));
}

// ---------------- 0) weight transpose + fp16 convert (all 4, 1 launch) -------
__global__ void __launch_bounds__(256) convw_k(const float* __restrict__ W0,
                                               const float* __restrict__ W1,
                                               const float* __restrict__ W2,
                                               const float* __restrict__ W3)
{
    __shared__ float tile[32][33];
    int wsel = blockIdx.z;
    const float* W = (wsel == 0) ? W0 : (wsel == 1) ? W1 : (wsel == 2) ? W2 : W3;
    __half* Th = g_wt[wsel];
    int mb = blockIdx.x * 32, kb = blockIdx.y * 32;
    int tx = threadIdx.x & 31, ty = threadIdx.x >> 5;   // 32 x 8
    #pragma unroll
    for (int i = 0; i < 32; i += 8)
        tile[ty + i][tx] = W[(mb + ty + i) * C_ + kb + tx];
    __syncthreads();
    #pragma unroll
    for (int i = 0; i < 32; i += 8)
        Th[(kb + ty + i) * C_ + mb + tx] = __float2half(tile[tx][ty + i]);
}

// ---------------- 1) channel layernorm, two-pass -> fp16 hi/lo ---------------
__global__ void __launch_bounds__(256) ln_k(const float* __restrict__ x,
                                            const float* __restrict__ g)
{
    __shared__ float rs[4][64], rss[4][64], smean[64], sinv[64];
    int base = blockIdx.x * 64;
    int b = base >> 12, hw0 = base & 4095;
    const float* xp = x + (size_t)b * C_ * HW + hw0;
    int tid = threadIdx.x;
    int p = tid & 63, cg = tid >> 6;

    const float* tp = xp + (size_t)(cg * 128) * HW + p;
    float s = 0.f, ss = 0.f;
    #pragma unroll 8
    for (int c2 = 0; c2 < 128; c2++) {
        float v = tp[(size_t)c2 * HW];
        s += v; ss += v * v;
    }
    rs[cg][p] = s; rss[cg][p] = ss;
    __syncthreads();
    if (tid < 64) {
        float st  = rs[0][tid] + rs[1][tid] + rs[2][tid] + rs[3][tid];
        float sst = rss[0][tid] + rss[1][tid] + rss[2][tid] + rss[3][tid];
        float mean = st * (1.f / C_);
        float var  = sst * (1.f / C_) - mean * mean;
        smean[tid] = mean;
        sinv[tid]  = rsqrtf(var + 1e-5f);
    }
    __syncthreads();

    float mean = smean[p], inv = sinv[p];
    size_t ob = (size_t)b * C_ * HW + hw0 + (size_t)(cg * 128) * HW + p;
    #pragma unroll 8
    for (int c2 = 0; c2 < 128; c2++) {
        float v = (tp[(size_t)c2 * HW] - mean) * inv * __ldg(g + cg * 128 + c2);
        __half h, l; split_fp16(v, h, l);
        g_fm_hi[ob + (size_t)c2 * HW] = h;
        g_fm_lo[ob + (size_t)c2 * HW] = l;
    }
}

// ---------------- 2) fp16x2 HMMA GEMM, 3-stage cp.async ----------------------
// D[m][n] = sum_k W[k][m] * (Bh + Bl)[k][n]; W single fp16, activations hi/lo.
#define STAGE_BYTES 49152          // A 16K | Bhi 16K | Blo 16K
#define NSTAGE 3

__global__ void __launch_bounds__(256, 1) gemm_fp16x2_k(
    const __half* __restrict__ Aw,
    const __half* __restrict__ Bh, const __half* __restrict__ Bl,
    float* __restrict__ Cg)
{
    extern __shared__ char sm[];
    const int N = HW;
    const int z = blockIdx.z;
    const __half* Bhp = Bh + (size_t)z * C_ * HW;
    const __half* Blp = Bl + (size_t)z * C_ * HW;
    float* Cp = Cg + (size_t)z * C_ * HW;
    const int m0 = blockIdx.y * 128, n0 = blockIdx.x * 128;
    const int tid = threadIdx.x;
    const int r0 = tid >> 4;
    const int cc = tid & 15;

    const int wid = tid >> 5, lane = tid & 31;
    const int warpM = (wid & 1) * 64, warpN = (wid >> 1) * 32;
    const int j = lane >> 3, lr = lane & 7;

    float acc[4][4][4];
    #pragma unroll
    for (int mt = 0; mt < 4; mt++)
        #pragma unroll
        for (int nt = 0; nt < 4; nt++)
            #pragma unroll
            for (int q = 0; q < 4; q++) acc[mt][nt][q] = 0.f;

    auto tile_copy = [&](int stage, int k0) {
        char* base = sm + stage * STAGE_BYTES;
        #pragma unroll
        for (int i = 0; i < 4; i++) {
            int r = r0 + i * 16;
            uint32_t dsto = r * 256 + ((cc ^ (r & 7)) << 4);
            cp16(smem_u32(base + dsto),          Aw  + (size_t)(k0 + r) * C_ + m0 + cc * 8);
            cp16(smem_u32(base + 16384 + dsto),  Bhp + (size_t)(k0 + r) * N  + n0 + cc * 8);
            cp16(smem_u32(base + 32768 + dsto),  Blp + (size_t)(k0 + r) * N  + n0 + cc * 8);
        }
        asm volatile("cp.async.commit_group;\n");
    };

    tile_copy(0, 0);
    tile_copy(1, 64);
    int stage_w = 2;
    for (int it = 0; it < 8; it++) {
        if (it + 2 < 8) {
            tile_copy(stage_w, (it + 2) * 64);
            stage_w = (stage_w + 1 == NSTAGE) ? 0 : stage_w + 1;
        } else {
            asm volatile("cp.async.commit_group;\n");
        }
        asm volatile("cp.async.wait_group 2;\n");
        __syncthreads();

        char* base = sm + (it % NSTAGE) * STAGE_BYTES;
        uint32_t aB  = smem_u32(base);
        uint32_t bHiB = aB + 16384;
        uint32_t bLoB = aB + 32768;

        #pragma unroll
        for (int kc = 0; kc < 4; kc++) {
            uint32_t aF[4][4], bHi[4][2], bLo[4][2];
            int arow = kc * 16 + ((j >> 1) << 3) + lr;
            int asw  = arow & 7;
            #pragma unroll
            for (int mt = 0; mt < 4; mt++) {
                int achunk = ((warpM + mt * 16) >> 3) + (j & 1);
                uint32_t off = arow * 256 + ((achunk ^ asw) << 4);
                ldsm4t(aF[mt][0], aF[mt][1], aF[mt][2], aF[mt][3], aB + off);
            }
            int brow = kc * 16 + ((j & 1) << 3) + lr;
            int bsw  = brow & 7;
            #pragma unroll
            for (int nt2 = 0; nt2 < 2; nt2++) {
                int bchunk = ((warpN + nt2 * 16) >> 3) + (j >> 1);
                uint32_t off = brow * 256 + ((bchunk ^ bsw) << 4);
                ldsm4t(bHi[nt2 * 2][0], bHi[nt2 * 2][1],
                       bHi[nt2 * 2 + 1][0], bHi[nt2 * 2 + 1][1], bHiB + off);
                ldsm4t(bLo[nt2 * 2][0], bLo[nt2 * 2][1],
                       bLo[nt2 * 2 + 1][0], bLo[nt2 * 2 + 1][1], bLoB + off);
            }
            #pragma unroll
            for (int mt = 0; mt < 4; mt++)
                #pragma unroll
                for (int nt = 0; nt < 4; nt++) {
                    mma16816(acc[mt][nt], aF[mt], bHi[nt]);
                    mma16816(acc[mt][nt], aF[mt], bLo[nt]);
                }
        }
        __syncthreads();
    }

    int ml = lane >> 2, nl = (lane & 3) * 2;
    #pragma unroll
    for (int mt = 0; mt < 4; mt++) {
        int m = m0 + warpM + mt * 16 + ml;
        #pragma unroll
        for (int nt = 0; nt < 4; nt++) {
            int n = n0 + warpN + nt * 8 + nl;
            *(float2*)&Cp[(size_t)m * N + n]       = make_float2(acc[mt][nt][0], acc[mt][nt][1]);
            *(float2*)&Cp[(size_t)(m + 8) * N + n] = make_float2(acc[mt][nt][2], acc[mt][nt][3]);
        }
    }
}

// ---------------- 3) depthwise 3x3 (single tensor) + optional k softmax ------
template <bool DO_SOFTMAX>
__global__ void __launch_bounds__(256) dw_k(const float* __restrict__ in,
                                            const float* __restrict__ w,
                                            float* __restrict__ out)
{
    __shared__ float sp[HW];
    __shared__ float red[256];
    int plane = blockIdx.x;
    int c = plane & 511;
    const float* ip = in + (size_t)plane * HW;
    float* op = out + (size_t)plane * HW;
    int tid = threadIdx.x;

    #pragma unroll
    for (int i = 0; i < 4; i++)
        ((float4*)sp)[tid + i * 256] = ((const float4*)ip)[tid + i * 256];
    float wr[9];
    #pragma unroll
    for (int i = 0; i < 9; i++) wr[i] = w[c * 9 + i];
    __syncthreads();

    const int x  = tid & 63;
    const int rg = tid >> 6;
    const int yb = rg * 16;
    const bool xm = (x > 0), xp_ok = (x < 63);

    float a0, a1, a2, b0, b1, b2;
    if (yb > 0) {
        const float* row = sp + (yb - 1) * 64;
        a0 = xm ? row[x - 1] : 0.f; a1 = row[x]; a2 = xp_ok ? row[x + 1] : 0.f;
    } else { a0 = a1 = a2 = 0.f; }
    {
        const float* row = sp + yb * 64;
        b0 = xm ? row[x - 1] : 0.f; b1 = row[x]; b2 = xp_ok ? row[x + 1] : 0.f;
    }

    float o[16];
    float mx = -1e30f;
    #pragma unroll
    for (int i = 0; i < 16; i++) {
        int y = yb + i;
        float c0, c1, c2;
        if (y + 1 <= 63) {
            const float* row = sp + (y + 1) * 64;
            c0 = xm ? row[x - 1] : 0.f; c1 = row[x]; c2 = xp_ok ? row[x + 1] : 0.f;
        } else { c0 = c1 = c2 = 0.f; }
        float acc = a0 * wr[0] + a1 * wr[1] + a2 * wr[2]
                  + b0 * wr[3] + b1 * wr[4] + b2 * wr[5]
                  + c0 * wr[6] + c1 * wr[7] + c2 * wr[8];
        o[i] = acc;
        mx = fmaxf(mx, acc);
        a0 = b0; a1 = b1; a2 = b2;
        b0 = c0; b1 = c1; b2 = c2;
    }

    if (DO_SOFTMAX) {
        red[tid] = mx; __syncthreads();
        #pragma unroll
        for (int s = 128; s > 0; s >>= 1) {
            if (tid < s) red[tid] = fmaxf(red[tid], red[tid + s]);
            __syncthreads();
        }
        mx = red[0];
        __syncthreads();
        float s = 0.f;
        #pragma unroll
        for (int i = 0; i < 16; i++) { o[i] = __expf(o[i] - mx); s += o[i]; }
        red[tid] = s; __syncthreads();
        #pragma unroll
        for (int st = 128; st > 0; st >>= 1) {
            if (tid < st) red[tid] += red[tid + st];
            __syncthreads();
        }
        float rcp = 1.f / red[0];
        #pragma unroll
        for (int i = 0; i < 16; i++) op[(yb + i) * 64 + x] = o[i] * rcp;
    } else {
        #pragma unroll
        for (int i = 0; i < 16; i++) op[(yb + i) * 64 + x] = o[i];
    }
}

// ---------------- 5) ctx split-K partials (pure FMA) -------------------------
__global__ void __launch_bounds__(256) ctx_k()
{
    int bh    = blockIdx.y;
    int split = blockIdx.x;
    int b = bh >> 3, h = bh & 7;
    int nbase = split * 256;
    const float* kp = g_kd + (size_t)(b * C_ + h * 64) * HW;
    const float* vp = g_vd + (size_t)(b * C_ + h * 64) * HW;
    __shared__ float kT[64][65];
    __shared__ float vT[64][65];
    int tid = threadIdx.x;
    int d0 = (tid >> 4) * 4;
    int e0 = (tid & 15) * 4;
    float acc[4][4];
    #pragma unroll
    for (int i = 0; i < 4; i++)
        #pragma unroll
        for (int jx = 0; jx < 4; jx++) acc[i][jx] = 0.f;

    for (int chunk = 0; chunk < 4; chunk++) {
        int n0 = nbase + chunk * 64;
        for (int i = tid; i < 64 * 64; i += 256) {
            int d = i >> 6, nn = i & 63;
            kT[d][nn] = kp[d * HW + n0 + nn];
            vT[d][nn] = vp[d * HW + n0 + nn];
        }
        __syncthreads();
        #pragma unroll 8
        for (int nn = 0; nn < 64; nn++) {
            float kr[4], vr[4];
            #pragma unroll
            for (int i = 0; i < 4; i++) { kr[i] = kT[d0 + i][nn]; vr[i] = vT[e0 + i][nn]; }
            #pragma unroll
            for (int i = 0; i < 4; i++)
                #pragma unroll
                for (int jx = 0; jx < 4; jx++)
                    acc[i][jx] += kr[i] * vr[jx];
        }
        __syncthreads();
    }
    float* cp = g_ctxp + ((size_t)split * NBH + bh) * 4096;
    #pragma unroll
    for (int i = 0; i < 4; i++)
        #pragma unroll
        for (int jx = 0; jx < 4; jx++)
            cp[(d0 + i) * 64 + (e0 + jx)] = acc[i][jx];
}

// ---------------- 5b) reduce split-K partials once ---------------------------
__global__ void __launch_bounds__(256) ctxred_k()
{
    int bh = blockIdx.x;
    int tid = threadIdx.x;
    #pragma unroll
    for (int i = 0; i < 16; i++) {
        int idx = tid + i * 256;
        float s = 0.f;
        #pragma unroll
        for (int sp = 0; sp < NSPLIT; sp++)
            s += g_ctxp[((size_t)sp * NBH + bh) * 4096 + idx];
        g_ctx[(size_t)bh * 4096 + idx] = s;
    }
}

// ---------------- 6) q softmax + q@ctx + silu -> fp16 hi/lo ------------------
__global__ void __launch_bounds__(256) attout_k()
{
    int bh = blockIdx.y;
    int b = bh >> 3, h = bh & 7;
    int n = blockIdx.x * 256 + threadIdx.x;
    __shared__ float ctx_s[64][64];
    for (int i = threadIdx.x; i < 4096; i += 256)
        ctx_s[i >> 6][i & 63] = g_ctx[(size_t)bh * 4096 + i];
    __syncthreads();

    const float* qp = g_qd + (size_t)(b * C_ + h * 64) * HW + n;
    float q[64];
    float m = -1e30f;
    #pragma unroll
    for (int d = 0; d < 64; d++) { q[d] = qp[d * HW]; m = fmaxf(m, q[d]); }
    float s = 0.f;
    #pragma unroll
    for (int d = 0; d < 64; d++) { q[d] = __expf(q[d] - m); s += q[d]; }
    float r = 0.125f / s;
    #pragma unroll
    for (int d = 0; d < 64; d++) q[d] *= r;

    size_t obase = (size_t)(b * C_ + h * 64) * HW + n;
    #pragma unroll
    for (int ec = 0; ec < 4; ec++) {
        float acc[16];
        #pragma unroll
        for (int jx = 0; jx < 16; jx++) acc[jx] = 0.f;
        #pragma unroll
        for (int d = 0; d < 64; d++) {
            float qd = q[d];
            const float* crow = &ctx_s[d][ec * 16];
            #pragma unroll
            for (int jx = 0; jx < 16; jx++) acc[jx] += qd * crow[jx];
        }
        #pragma unroll
        for (int jx = 0; jx < 16; jx++) {
            float xv = acc[jx];
            float sg = 1.f / (1.f + __expf(-xv));
            float ov = xv * sg;
            __half hh, ll; split_fp16(ov, hh, ll);
            g_att_hi[obase + (size_t)(ec * 16 + jx) * HW] = hh;
            g_att_lo[obase + (size_t)(ec * 16 + jx) * HW] = ll;
        }
    }
}

// ---------------- host orchestration -----------------------------------------
template <typename T>
static T* symaddr(const void* sym)
{
    void* p = nullptr;
    cudaGetSymbolAddress(&p, sym);
    return (T*)p;
}

extern "C" void kernel_launch(void* const* d_in, const int* in_sizes, int n_in,
                              void* d_out, int out_size)
{
    const float* fmap = (const float*)d_in[0];
    const float* g    = (const float*)d_in[1];
    const float* wq1  = (const float*)d_in[2];
    const float* wqdw = (const float*)d_in[3];
    const float* wk1  = (const float*)d_in[4];
    const float* wkdw = (const float*)d_in[5];
    const float* wv1  = (const float*)d_in[6];
    const float* wvdw = (const float*)d_in[7];
    const float* wout = (const float*)d_in[8];
    float* out = (float*)d_out;

    __half* fmh = symaddr<__half>(g_fm_hi);
    __half* fml = symaddr<__half>(g_fm_lo);
    __half* ath = symaddr<__half>(g_att_hi);
    __half* atl = symaddr<__half>(g_att_lo);
    __half* wt  = symaddr<__half>(g_wt);
    float* q0  = symaddr<float>(g_q0);
    float* k0  = symaddr<float>(g_k0);
    float* v0  = symaddr<float>(g_v0);
    float* qd  = symaddr<float>(g_qd);
    float* kd  = symaddr<float>(g_kd);
    float* vd  = symaddr<float>(g_vd);

    cudaFuncSetAttribute(gemm_fp16x2_k,
                         cudaFuncAttributeMaxDynamicSharedMemorySize, NSTAGE * STAGE_BYTES);

    cudaStream_t s0 = 0;          // capture stream
    cudaStream_t s2 = g_s2;

    // fork: side stream joins capture via event recorded on s0
    cudaEventRecord(g_evRoot, s0);
    cudaStreamWaitEvent(s2, g_evRoot, 0);

    // side: weight prep (overlaps ln on s0)
    convw_k<<<dim3(16, 16, 4), 256, 0, s2>>>(wq1, wk1, wv1, wout);
    cudaEventRecord(g_evW, s2);

    // main: layernorm
    ln_k<<<512, 256, 0, s0>>>(fmap, g);
    cudaStreamWaitEvent(s0, g_evW, 0);

    dim3 gg(HW / 128, C_ / 128, B_);

    // main: GEMM chain k -> v -> q
    gemm_fp16x2_k<<<gg, 256, NSTAGE * STAGE_BYTES, s0>>>(wt + 1 * C_ * C_, fmh, fml, k0);
    cudaEventRecord(g_evK, s0);
    gemm_fp16x2_k<<<gg, 256, NSTAGE * STAGE_BYTES, s0>>>(wt + 2 * C_ * C_, fmh, fml, v0);
    cudaEventRecord(g_evV, s0);
    gemm_fp16x2_k<<<gg, 256, NSTAGE * STAGE_BYTES, s0>>>(wt + 0 * C_ * C_, fmh, fml, q0);
    cudaEventRecord(g_evQ, s0);

    // side stream: glue overlapped with GEMMs (now co-resident: 144K + 17K)
    cudaStreamWaitEvent(s2, g_evK, 0);
    dw_k<true><<<B_ * C_, 256, 0, s2>>>(k0, wkdw, kd);          // overlaps GEMM_v
    cudaStreamWaitEvent(s2, g_evV, 0);
    dw_k<false><<<B_ * C_, 256, 0, s2>>>(v0, wvdw, vd);         // overlaps GEMM_q
    ctx_k<<<dim3(NSPLIT, NBH), 256, 0, s2>>>();                 // overlaps GEMM_q
    ctxred_k<<<NBH, 256, 0, s2>>>();                            // overlaps GEMM_q
    cudaStreamWaitEvent(s2, g_evQ, 0);
    dw_k<false><<<B_ * C_, 256, 0, s2>>>(q0, wqdw, qd);
    attout_k<<<dim3(HW / 256, NBH), 256, 0, s2>>>();
    cudaEventRecord(g_evA, s2);

    // main: final pointwise conv -> d_out (join)
    cudaStreamWaitEvent(s0, g_evA, 0);
    gemm_fp16x2_k<<<gg, 256, NSTAGE * STAGE_BYTES, s0>>>(wt + 3 * C_ * C_, ath, atl, out);

    (void)in_sizes; (void)n_in; (void)out_size;
}

// round 17
// speedup vs baseline: 1.5327x; 1.2390x over previous
#include <cuda_runtime.h>
#include <cuda_bf16.h>
#include <cuda_fp16.h>
#include <math.h>
#include <stdint.h>

#define B_    8
#define C_    512
#define HW    4096            // 64*64
#define NPIX  (B_*HW)         // 32768
#define ELEMS (B_*C_*HW)      // 16777216
#define NBH   64              // B_*heads
#define NSPLIT 16

// ---------------- scratch (static device memory; no runtime allocation) ------
__device__ __half g_fm [ELEMS];                  // ln output, fp16
__device__ __half g_att[ELEMS];                  // attention output, fp16
__device__ float g_q0 [ELEMS];
__device__ float g_k0 [ELEMS];
__device__ float g_v0 [ELEMS];
__device__ float g_qd [ELEMS];
__device__ float g_kd [ELEMS];     // softmax-normalized dwconv(k)
__device__ float g_vd [ELEMS];
__device__ float g_ctxp[NSPLIT * NBH * 64 * 64];
__device__ float g_ctx [NBH * 64 * 64];          // reduced ctx
__device__ __half g_wt[4][C_ * C_];              // [k][m] fp16, q|k|v|out

// ---------------- streams/events (created pre-main, reused every call) -------
static cudaStream_t g_s2 = nullptr;
static cudaEvent_t  g_evRoot, g_evW, g_evK, g_evV, g_evQ, g_evA;
struct StreamInit {
    StreamInit() {
        cudaStreamCreateWithFlags(&g_s2, cudaStreamNonBlocking);
        cudaEventCreateWithFlags(&g_evRoot, cudaEventDisableTiming);
        cudaEventCreateWithFlags(&g_evW, cudaEventDisableTiming);
        cudaEventCreateWithFlags(&g_evK, cudaEventDisableTiming);
        cudaEventCreateWithFlags(&g_evV, cudaEventDisableTiming);
        cudaEventCreateWithFlags(&g_evQ, cudaEventDisableTiming);
        cudaEventCreateWithFlags(&g_evA, cudaEventDisableTiming);
    }
};
static StreamInit g_stream_init;

// ---------------- PTX helpers -------------------------------------------------
__device__ __forceinline__ uint32_t smem_u32(const void* p) {
    return (uint32_t)__cvta_generic_to_shared(p);
}
__device__ __forceinline__ void cp16(uint32_t dst, const void* src) {
    asm volatile("cp.async.cg.shared.global [%0], [%1], 16;\n" :: "r"(dst), "l"(src));
}
__device__ __forceinline__ void ldsm4t(uint32_t& r0, uint32_t& r1, uint32_t& r2, uint32_t& r3,
                                       uint32_t addr) {
    asm volatile("ldmatrix.sync.aligned.m8n8.x4.trans.shared.b16 {%0,%1,%2,%3}, [%4];\n"
                 : "=r"(r0), "=r"(r1), "=r"(r2), "=r"(r3) : "r"(addr));
}
__device__ __forceinline__ void mma16816(float* c, const uint32_t* a, const uint32_t* b) {
    asm volatile("mma.sync.aligned.m16n8k16.row.col.f32.f16.f16.f32 "
                 "{%0,%1,%2,%3}, {%4,%5,%6,%7}, {%8,%9}, {%0,%1,%2,%3};\n"
                 : "+f"(c[0]), "+f"(c[1]), "+f"(c[2]), "+f"(c[3])
                 : "r"(a[0]), "r"(a[1]), "r"(a[2]), "r"(a[3]), "r"(b[0]), "r"(b[1]));
}

// ---------------- 0) weight transpose + fp16 convert (all 4, 1 launch) -------
__global__ void __launch_bounds__(256) convw_k(const float* __restrict__ W0,
                                               const float* __restrict__ W1,
                                               const float* __restrict__ W2,
                                               const float* __restrict__ W3)
{
    __shared__ float tile[32][33];
    int wsel = blockIdx.z;
    const float* W = (wsel == 0) ? W0 : (wsel == 1) ? W1 : (wsel == 2) ? W2 : W3;
    __half* Th = g_wt[wsel];
    int mb = blockIdx.x * 32, kb = blockIdx.y * 32;
    int tx = threadIdx.x & 31, ty = threadIdx.x >> 5;   // 32 x 8
    #pragma unroll
    for (int i = 0; i < 32; i += 8)
        tile[ty + i][tx] = W[(mb + ty + i) * C_ + kb + tx];
    __syncthreads();
    #pragma unroll
    for (int i = 0; i < 32; i += 8)
        Th[(kb + ty + i) * C_ + mb + tx] = __float2half(tile[tx][ty + i]);
}

// ---------------- 1) channel layernorm, two-pass -> fp16 ---------------------
__global__ void __launch_bounds__(256) ln_k(const float* __restrict__ x,
                                            const float* __restrict__ g)
{
    __shared__ float rs[4][64], rss[4][64], smean[64], sinv[64];
    int base = blockIdx.x * 64;
    int b = base >> 12, hw0 = base & 4095;
    const float* xp = x + (size_t)b * C_ * HW + hw0;
    int tid = threadIdx.x;
    int p = tid & 63, cg = tid >> 6;

    const float* tp = xp + (size_t)(cg * 128) * HW + p;
    float s = 0.f, ss = 0.f;
    #pragma unroll 8
    for (int c2 = 0; c2 < 128; c2++) {
        float v = tp[(size_t)c2 * HW];
        s += v; ss += v * v;
    }
    rs[cg][p] = s; rss[cg][p] = ss;
    __syncthreads();
    if (tid < 64) {
        float st  = rs[0][tid] + rs[1][tid] + rs[2][tid] + rs[3][tid];
        float sst = rss[0][tid] + rss[1][tid] + rss[2][tid] + rss[3][tid];
        float mean = st * (1.f / C_);
        float var  = sst * (1.f / C_) - mean * mean;
        smean[tid] = mean;
        sinv[tid]  = rsqrtf(var + 1e-5f);
    }
    __syncthreads();

    float mean = smean[p], inv = sinv[p];
    size_t ob = (size_t)b * C_ * HW + hw0 + (size_t)(cg * 128) * HW + p;
    #pragma unroll 8
    for (int c2 = 0; c2 < 128; c2++) {
        float v = (tp[(size_t)c2 * HW] - mean) * inv * __ldg(g + cg * 128 + c2);
        g_fm[ob + (size_t)c2 * HW] = __float2half(v);
    }
}

// ---------------- 2) fp16 HMMA GEMM, 3-stage cp.async ------------------------
// D[m][n] = sum_k W[k][m] * X[k][n]; both operands single fp16.
#define STAGE_BYTES 32768          // A 16K | B 16K
#define NSTAGE 3

__global__ void __launch_bounds__(256, 1) gemm_fp16_k(
    const __half* __restrict__ Aw, const __half* __restrict__ Bx,
    float* __restrict__ Cg)
{
    extern __shared__ char sm[];
    const int N = HW;
    const int z = blockIdx.z;
    const __half* Bp = Bx + (size_t)z * C_ * HW;
    float* Cp = Cg + (size_t)z * C_ * HW;
    const int m0 = blockIdx.y * 128, n0 = blockIdx.x * 128;
    const int tid = threadIdx.x;
    const int r0 = tid >> 4;
    const int cc = tid & 15;

    const int wid = tid >> 5, lane = tid & 31;
    const int warpM = (wid & 1) * 64, warpN = (wid >> 1) * 32;
    const int j = lane >> 3, lr = lane & 7;

    float acc[4][4][4];
    #pragma unroll
    for (int mt = 0; mt < 4; mt++)
        #pragma unroll
        for (int nt = 0; nt < 4; nt++)
            #pragma unroll
            for (int q = 0; q < 4; q++) acc[mt][nt][q] = 0.f;

    auto tile_copy = [&](int stage, int k0) {
        char* base = sm + stage * STAGE_BYTES;
        #pragma unroll
        for (int i = 0; i < 4; i++) {
            int r = r0 + i * 16;
            uint32_t dsto = r * 256 + ((cc ^ (r & 7)) << 4);
            cp16(smem_u32(base + dsto),          Aw + (size_t)(k0 + r) * C_ + m0 + cc * 8);
            cp16(smem_u32(base + 16384 + dsto),  Bp + (size_t)(k0 + r) * N  + n0 + cc * 8);
        }
        asm volatile("cp.async.commit_group;\n");
    };

    tile_copy(0, 0);
    tile_copy(1, 64);
    int stage_w = 2;
    for (int it = 0; it < 8; it++) {
        if (it + 2 < 8) {
            tile_copy(stage_w, (it + 2) * 64);
            stage_w = (stage_w + 1 == NSTAGE) ? 0 : stage_w + 1;
        } else {
            asm volatile("cp.async.commit_group;\n");
        }
        asm volatile("cp.async.wait_group 2;\n");
        __syncthreads();

        char* base = sm + (it % NSTAGE) * STAGE_BYTES;
        uint32_t aB = smem_u32(base);
        uint32_t bB = aB + 16384;

        #pragma unroll
        for (int kc = 0; kc < 4; kc++) {
            uint32_t aF[4][4], bF[4][2];
            int arow = kc * 16 + ((j >> 1) << 3) + lr;
            int asw  = arow & 7;
            #pragma unroll
            for (int mt = 0; mt < 4; mt++) {
                int achunk = ((warpM + mt * 16) >> 3) + (j & 1);
                uint32_t off = arow * 256 + ((achunk ^ asw) << 4);
                ldsm4t(aF[mt][0], aF[mt][1], aF[mt][2], aF[mt][3], aB + off);
            }
            int brow = kc * 16 + ((j & 1) << 3) + lr;
            int bsw  = brow & 7;
            #pragma unroll
            for (int nt2 = 0; nt2 < 2; nt2++) {
                int bchunk = ((warpN + nt2 * 16) >> 3) + (j >> 1);
                uint32_t off = brow * 256 + ((bchunk ^ bsw) << 4);
                ldsm4t(bF[nt2 * 2][0], bF[nt2 * 2][1],
                       bF[nt2 * 2 + 1][0], bF[nt2 * 2 + 1][1], bB + off);
            }
            #pragma unroll
            for (int mt = 0; mt < 4; mt++)
                #pragma unroll
                for (int nt = 0; nt < 4; nt++)
                    mma16816(acc[mt][nt], aF[mt], bF[nt]);
        }
        __syncthreads();
    }

    int ml = lane >> 2, nl = (lane & 3) * 2;
    #pragma unroll
    for (int mt = 0; mt < 4; mt++) {
        int m = m0 + warpM + mt * 16 + ml;
        #pragma unroll
        for (int nt = 0; nt < 4; nt++) {
            int n = n0 + warpN + nt * 8 + nl;
            *(float2*)&Cp[(size_t)m * N + n]       = make_float2(acc[mt][nt][0], acc[mt][nt][1]);
            *(float2*)&Cp[(size_t)(m + 8) * N + n] = make_float2(acc[mt][nt][2], acc[mt][nt][3]);
        }
    }
}

// ---------------- 3) depthwise 3x3 (single tensor) + optional k softmax ------
template <bool DO_SOFTMAX>
__global__ void __launch_bounds__(256) dw_k(const float* __restrict__ in,
                                            const float* __restrict__ w,
                                            float* __restrict__ out)
{
    __shared__ float sp[HW];
    __shared__ float red[256];
    int plane = blockIdx.x;
    int c = plane & 511;
    const float* ip = in + (size_t)plane * HW;
    float* op = out + (size_t)plane * HW;
    int tid = threadIdx.x;

    #pragma unroll
    for (int i = 0; i < 4; i++)
        ((float4*)sp)[tid + i * 256] = ((const float4*)ip)[tid + i * 256];
    float wr[9];
    #pragma unroll
    for (int i = 0; i < 9; i++) wr[i] = w[c * 9 + i];
    __syncthreads();

    const int x  = tid & 63;
    const int rg = tid >> 6;
    const int yb = rg * 16;
    const bool xm = (x > 0), xp_ok = (x < 63);

    float a0, a1, a2, b0, b1, b2;
    if (yb > 0) {
        const float* row = sp + (yb - 1) * 64;
        a0 = xm ? row[x - 1] : 0.f; a1 = row[x]; a2 = xp_ok ? row[x + 1] : 0.f;
    } else { a0 = a1 = a2 = 0.f; }
    {
        const float* row = sp + yb * 64;
        b0 = xm ? row[x - 1] : 0.f; b1 = row[x]; b2 = xp_ok ? row[x + 1] : 0.f;
    }

    float o[16];
    float mx = -1e30f;
    #pragma unroll
    for (int i = 0; i < 16; i++) {
        int y = yb + i;
        float c0, c1, c2;
        if (y + 1 <= 63) {
            const float* row = sp + (y + 1) * 64;
            c0 = xm ? row[x - 1] : 0.f; c1 = row[x]; c2 = xp_ok ? row[x + 1] : 0.f;
        } else { c0 = c1 = c2 = 0.f; }
        float acc = a0 * wr[0] + a1 * wr[1] + a2 * wr[2]
                  + b0 * wr[3] + b1 * wr[4] + b2 * wr[5]
                  + c0 * wr[6] + c1 * wr[7] + c2 * wr[8];
        o[i] = acc;
        mx = fmaxf(mx, acc);
        a0 = b0; a1 = b1; a2 = b2;
        b0 = c0; b1 = c1; b2 = c2;
    }

    if (DO_SOFTMAX) {
        red[tid] = mx; __syncthreads();
        #pragma unroll
        for (int s = 128; s > 0; s >>= 1) {
            if (tid < s) red[tid] = fmaxf(red[tid], red[tid + s]);
            __syncthreads();
        }
        mx = red[0];
        __syncthreads();
        float s = 0.f;
        #pragma unroll
        for (int i = 0; i < 16; i++) { o[i] = __expf(o[i] - mx); s += o[i]; }
        red[tid] = s; __syncthreads();
        #pragma unroll
        for (int st = 128; st > 0; st >>= 1) {
            if (tid < st) red[tid] += red[tid + st];
            __syncthreads();
        }
        float rcp = 1.f / red[0];
        #pragma unroll
        for (int i = 0; i < 16; i++) op[(yb + i) * 64 + x] = o[i] * rcp;
    } else {
        #pragma unroll
        for (int i = 0; i < 16; i++) op[(yb + i) * 64 + x] = o[i];
    }
}

// ---------------- 5) ctx split-K partials (pure FMA) -------------------------
__global__ void __launch_bounds__(256) ctx_k()
{
    int bh    = blockIdx.y;
    int split = blockIdx.x;
    int b = bh >> 3, h = bh & 7;
    int nbase = split * 256;
    const float* kp = g_kd + (size_t)(b * C_ + h * 64) * HW;
    const float* vp = g_vd + (size_t)(b * C_ + h * 64) * HW;
    __shared__ float kT[64][65];
    __shared__ float vT[64][65];
    int tid = threadIdx.x;
    int d0 = (tid >> 4) * 4;
    int e0 = (tid & 15) * 4;
    float acc[4][4];
    #pragma unroll
    for (int i = 0; i < 4; i++)
        #pragma unroll
        for (int jx = 0; jx < 4; jx++) acc[i][jx] = 0.f;

    for (int chunk = 0; chunk < 4; chunk++) {
        int n0 = nbase + chunk * 64;
        for (int i = tid; i < 64 * 64; i += 256) {
            int d = i >> 6, nn = i & 63;
            kT[d][nn] = kp[d * HW + n0 + nn];
            vT[d][nn] = vp[d * HW + n0 + nn];
        }
        __syncthreads();
        #pragma unroll 8
        for (int nn = 0; nn < 64; nn++) {
            float kr[4], vr[4];
            #pragma unroll
            for (int i = 0; i < 4; i++) { kr[i] = kT[d0 + i][nn]; vr[i] = vT[e0 + i][nn]; }
            #pragma unroll
            for (int i = 0; i < 4; i++)
                #pragma unroll
                for (int jx = 0; jx < 4; jx++)
                    acc[i][jx] += kr[i] * vr[jx];
        }
        __syncthreads();
    }
    float* cp = g_ctxp + ((size_t)split * NBH + bh) * 4096;
    #pragma unroll
    for (int i = 0; i < 4; i++)
        #pragma unroll
        for (int jx = 0; jx < 4; jx++)
            cp[(d0 + i) * 64 + (e0 + jx)] = acc[i][jx];
}

// ---------------- 5b) reduce split-K partials once ---------------------------
__global__ void __launch_bounds__(256) ctxred_k()
{
    int bh = blockIdx.x;
    int tid = threadIdx.x;
    #pragma unroll
    for (int i = 0; i < 16; i++) {
        int idx = tid + i * 256;
        float s = 0.f;
        #pragma unroll
        for (int sp = 0; sp < NSPLIT; sp++)
            s += g_ctxp[((size_t)sp * NBH + bh) * 4096 + idx];
        g_ctx[(size_t)bh * 4096 + idx] = s;
    }
}

// ---------------- 6) q softmax + q@ctx + silu -> fp16 ------------------------
__global__ void __launch_bounds__(256) attout_k()
{
    int bh = blockIdx.y;
    int b = bh >> 3, h = bh & 7;
    int n = blockIdx.x * 256 + threadIdx.x;
    __shared__ float ctx_s[64][64];
    for (int i = threadIdx.x; i < 4096; i += 256)
        ctx_s[i >> 6][i & 63] = g_ctx[(size_t)bh * 4096 + i];
    __syncthreads();

    const float* qp = g_qd + (size_t)(b * C_ + h * 64) * HW + n;
    float q[64];
    float m = -1e30f;
    #pragma unroll
    for (int d = 0; d < 64; d++) { q[d] = qp[d * HW]; m = fmaxf(m, q[d]); }
    float s = 0.f;
    #pragma unroll
    for (int d = 0; d < 64; d++) { q[d] = __expf(q[d] - m); s += q[d]; }
    float r = 0.125f / s;
    #pragma unroll
    for (int d = 0; d < 64; d++) q[d] *= r;

    size_t obase = (size_t)(b * C_ + h * 64) * HW + n;
    #pragma unroll
    for (int ec = 0; ec < 4; ec++) {
        float acc[16];
        #pragma unroll
        for (int jx = 0; jx < 16; jx++) acc[jx] = 0.f;
        #pragma unroll
        for (int d = 0; d < 64; d++) {
            float qd = q[d];
            const float* crow = &ctx_s[d][ec * 16];
            #pragma unroll
            for (int jx = 0; jx < 16; jx++) acc[jx] += qd * crow[jx];
        }
        #pragma unroll
        for (int jx = 0; jx < 16; jx++) {
            float xv = acc[jx];
            float sg = 1.f / (1.f + __expf(-xv));
            g_att[obase + (size_t)(ec * 16 + jx) * HW] = __float2half(xv * sg);
        }
    }
}

// ---------------- host orchestration -----------------------------------------
template <typename T>
static T* symaddr(const void* sym)
{
    void* p = nullptr;
    cudaGetSymbolAddress(&p, sym);
    return (T*)p;
}

extern "C" void kernel_launch(void* const* d_in, const int* in_sizes, int n_in,
                              void* d_out, int out_size)
{
    const float* fmap = (const float*)d_in[0];
    const float* g    = (const float*)d_in[1];
    const float* wq1  = (const float*)d_in[2];
    const float* wqdw = (const float*)d_in[3];
    const float* wk1  = (const float*)d_in[4];
    const float* wkdw = (const float*)d_in[5];
    const float* wv1  = (const float*)d_in[6];
    const float* wvdw = (const float*)d_in[7];
    const float* wout = (const float*)d_in[8];
    float* out = (float*)d_out;

    __half* fm  = symaddr<__half>(g_fm);
    __half* att = symaddr<__half>(g_att);
    __half* wt  = symaddr<__half>(g_wt);
    float* q0  = symaddr<float>(g_q0);
    float* k0  = symaddr<float>(g_k0);
    float* v0  = symaddr<float>(g_v0);
    float* qd  = symaddr<float>(g_qd);
    float* kd  = symaddr<float>(g_kd);
    float* vd  = symaddr<float>(g_vd);

    cudaFuncSetAttribute(gemm_fp16_k,
                         cudaFuncAttributeMaxDynamicSharedMemorySize, NSTAGE * STAGE_BYTES);

    cudaStream_t s0 = 0;          // capture stream
    cudaStream_t s2 = g_s2;

    // fork: side stream joins capture via event recorded on s0
    cudaEventRecord(g_evRoot, s0);
    cudaStreamWaitEvent(s2, g_evRoot, 0);

    // side: weight prep (overlaps ln on s0)
    convw_k<<<dim3(16, 16, 4), 256, 0, s2>>>(wq1, wk1, wv1, wout);
    cudaEventRecord(g_evW, s2);

    // main: layernorm
    ln_k<<<512, 256, 0, s0>>>(fmap, g);
    cudaStreamWaitEvent(s0, g_evW, 0);

    dim3 gg(HW / 128, C_ / 128, B_);

    // main: GEMM chain k -> v -> q
    gemm_fp16_k<<<gg, 256, NSTAGE * STAGE_BYTES, s0>>>(wt + 1 * C_ * C_, fm, k0);
    cudaEventRecord(g_evK, s0);
    gemm_fp16_k<<<gg, 256, NSTAGE * STAGE_BYTES, s0>>>(wt + 2 * C_ * C_, fm, v0);
    cudaEventRecord(g_evV, s0);
    gemm_fp16_k<<<gg, 256, NSTAGE * STAGE_BYTES, s0>>>(wt + 0 * C_ * C_, fm, q0);
    cudaEventRecord(g_evQ, s0);

    // side stream: glue overlapped with GEMMs (96K GEMM + 17K glue co-resident)
    cudaStreamWaitEvent(s2, g_evK, 0);
    dw_k<true><<<B_ * C_, 256, 0, s2>>>(k0, wkdw, kd);          // overlaps GEMM_v
    cudaStreamWaitEvent(s2, g_evV, 0);
    dw_k<false><<<B_ * C_, 256, 0, s2>>>(v0, wvdw, vd);         // overlaps GEMM_q
    ctx_k<<<dim3(NSPLIT, NBH), 256, 0, s2>>>();                 // overlaps GEMM_q
    ctxred_k<<<NBH, 256, 0, s2>>>();                            // overlaps GEMM_q
    cudaStreamWaitEvent(s2, g_evQ, 0);
    dw_k<false><<<B_ * C_, 256, 0, s2>>>(q0, wqdw, qd);
    attout_k<<<dim3(HW / 256, NBH), 256, 0, s2>>>();
    cudaEventRecord(g_evA, s2);

    // main: final pointwise conv -> d_out (join)
    cudaStreamWaitEvent(s0, g_evA, 0);
    gemm_fp16_k<<<gg, 256, NSTAGE * STAGE_BYTES, s0>>>(wt + 3 * C_ * C_, att, out);

    (void)in_sizes; (void)n_in; (void)out_size;
}